// round 7
// baseline (speedup 1.0000x reference)
#include <cuda_runtime.h>
#include <math.h>

#define BATCH  256
#define NBLK   64
#define DMODEL 512
#define HDIM   512
#define NHEAD  8
#define DK     64

typedef unsigned long long u64;

// Scratch (allocation-free rule: __device__ globals)
__device__ float g_qh[BATCH * NBLK * HDIM];
__device__ float g_kh[BATCH * NBLK * HDIM];
__device__ float g_vh[BATCH * NBLK * HDIM];
__device__ float g_ctx[BATCH * NBLK * HDIM];

// ---- packed fp32x2 helpers (sm_103a FFMA2 path) ----
__device__ __forceinline__ u64 pack2(float x, float y) {
    u64 r; asm("mov.b64 %0, {%1, %2};" : "=l"(r) : "f"(x), "f"(y)); return r;
}
__device__ __forceinline__ void unpack2(u64 v, float& x, float& y) {
    asm("mov.b64 {%0, %1}, %2;" : "=f"(x), "=f"(y) : "l"(v));
}
__device__ __forceinline__ void ffma2(u64& d, u64 a, u64 b) {
    asm("fma.rn.f32x2 %0, %1, %2, %3;" : "=l"(d) : "l"(a), "l"(b), "l"(d));
}

// ---------------------------------------------------------------------------
// Kernel 1: batched projections. 192 GEMMs: C[g] = A_rows(:, n fixed) x W[n]
//   qh[b,n,o] = sum_d q[b,n,d] * Wq[n,d,o]   (and same for k, v)
// Block tile 128x128, K-tile 16, 8x8 per thread via FFMA2, 256 threads.
// Double-buffered SMEM: ONE barrier per k-tile; LDG->STS separated by the
// whole compute block so global latency is fully hidden.
// grid = (4 ntiles, 2 mtiles, 192 g)  with g = which*64 + n
// ---------------------------------------------------------------------------
__global__ __launch_bounds__(256) void proj_kernel(
    const float* __restrict__ q, const float* __restrict__ k, const float* __restrict__ v,
    const float* __restrict__ Wq, const float* __restrict__ Wk, const float* __restrict__ Wv)
{
    int g = blockIdx.z;
    int which = g >> 6;
    int n = g & 63;
    const float* A;
    const float* W;
    float* C;
    if (which == 0)      { A = q; W = Wq; C = g_qh; }
    else if (which == 1) { A = k; W = Wk; C = g_kh; }
    else                 { A = v; W = Wv; C = g_vh; }
    W += (size_t)n * DMODEL * HDIM;

    __shared__ float As[2][16][128];
    __shared__ float Bs[2][16][128];

    int tid  = threadIdx.x;
    int tm   = tid >> 4;          // 0..15
    int tn   = tid & 15;          // 0..15
    int arow = tid >> 1;          // 0..127
    int akk  = (tid & 1) << 2;    // 0 or 4  (second chunk at +8)
    int brow = tid >> 5;          // 0..7    (second at +8)
    int bcol = (tid & 31) << 2;   // 0..124

    int m0 = blockIdx.y * 128;
    int n0 = blockIdx.x * 128;

    const float* Ap = A + ((size_t)(m0 + arow) * NBLK + n) * DMODEL + akk;
    const float* Bp = W + (size_t)brow * HDIM + n0 + bcol;

    u64 acc2[8][4];
#pragma unroll
    for (int i = 0; i < 8; i++)
#pragma unroll
        for (int j = 0; j < 4; j++) acc2[i][j] = 0ULL;

    // prologue: load + store tile 0 into buffer 0
    {
        float4 av0 = *(const float4*)(Ap);
        float4 av1 = *(const float4*)(Ap + 8);
        float4 bv0 = *(const float4*)(Bp);
        float4 bv1 = *(const float4*)(Bp + (size_t)8 * HDIM);
        As[0][akk + 0][arow]  = av0.x;
        As[0][akk + 1][arow]  = av0.y;
        As[0][akk + 2][arow]  = av0.z;
        As[0][akk + 3][arow]  = av0.w;
        As[0][akk + 8][arow]  = av1.x;
        As[0][akk + 9][arow]  = av1.y;
        As[0][akk + 10][arow] = av1.z;
        As[0][akk + 11][arow] = av1.w;
        *(float4*)&Bs[0][brow][bcol]     = bv0;
        *(float4*)&Bs[0][brow + 8][bcol] = bv1;
    }
    __syncthreads();

#pragma unroll 1
    for (int k0 = 0; k0 < DMODEL; k0 += 16) {
        int cur = (k0 >> 4) & 1;
        int nxt = cur ^ 1;
        bool have_next = (k0 + 16 < DMODEL);

        // issue next tile's global loads first (consumed only after compute)
        float4 av0, av1, bv0, bv1;
        if (have_next) {
            av0 = *(const float4*)(Ap + k0 + 16);
            av1 = *(const float4*)(Ap + k0 + 24);
            bv0 = *(const float4*)(Bp + (size_t)(k0 + 16) * HDIM);
            bv1 = *(const float4*)(Bp + (size_t)(k0 + 24) * HDIM);
        }

#pragma unroll
        for (int kk = 0; kk < 16; kk++) {
            float a[8];
            *(float4*)(a)     = *(const float4*)&As[cur][kk][tm * 8];
            *(float4*)(a + 4) = *(const float4*)&As[cur][kk][tm * 8 + 4];
            u64 b2[4];
            b2[0] = *(const u64*)&Bs[cur][kk][tn * 8 + 0];   // LDS.64 pre-packed
            b2[1] = *(const u64*)&Bs[cur][kk][tn * 8 + 2];
            b2[2] = *(const u64*)&Bs[cur][kk][tn * 8 + 4];
            b2[3] = *(const u64*)&Bs[cur][kk][tn * 8 + 6];
#pragma unroll
            for (int i = 0; i < 8; i++) {
                u64 a2 = pack2(a[i], a[i]);
#pragma unroll
                for (int j = 0; j < 4; j++)
                    ffma2(acc2[i][j], a2, b2[j]);
            }
        }

        if (have_next) {
            As[nxt][akk + 0][arow]  = av0.x;
            As[nxt][akk + 1][arow]  = av0.y;
            As[nxt][akk + 2][arow]  = av0.z;
            As[nxt][akk + 3][arow]  = av0.w;
            As[nxt][akk + 8][arow]  = av1.x;
            As[nxt][akk + 9][arow]  = av1.y;
            As[nxt][akk + 10][arow] = av1.z;
            As[nxt][akk + 11][arow] = av1.w;
            *(float4*)&Bs[nxt][brow][bcol]     = bv0;
            *(float4*)&Bs[nxt][brow + 8][bcol] = bv1;
            __syncthreads();   // one barrier per k-tile
        }
    }

#pragma unroll
    for (int i = 0; i < 8; i++) {
        size_t row = (size_t)(m0 + tm * 8 + i);
        float* Cp = C + (row * NBLK + n) * HDIM + n0 + tn * 8;
        float c0, c1, c2, c3, c4, c5, c6, c7;
        unpack2(acc2[i][0], c0, c1);
        unpack2(acc2[i][1], c2, c3);
        unpack2(acc2[i][2], c4, c5);
        unpack2(acc2[i][3], c6, c7);
        *(float4*)Cp       = make_float4(c0, c1, c2, c3);
        *(float4*)(Cp + 4) = make_float4(c4, c5, c6, c7);
    }
}

// ---------------------------------------------------------------------------
// Kernel 2: attention per (b,h). 2048 blocks x 64 threads.
// S = QK^T/8 -> softmax -> top5 sparsify + renorm -> write attn + sparse P*V.
// Top-5 via branch-free sorted-5-tuple cascade (v4 == jax top_k vals[-1],
// duplicates counted). After clamp at delta = v4+eps at most 4 weights
// survive, so P*V iterates only over the survivors.
// ---------------------------------------------------------------------------
__global__ __launch_bounds__(64) void attn_kernel(float* __restrict__ attn_out)
{
    int bh = blockIdx.x;
    int b = bh >> 3;
    int h = bh & 7;

    __shared__ float Kt[64][66];   // transposed K; stride 66 keeps u64 loads aligned
    __shared__ float Vs[64][64];

    int t = threadIdx.x;
    size_t base = (size_t)b * 64 * HDIM + h * DK;

    for (int idx = t; idx < 64 * 16; idx += 64) {
        int r = idx >> 4;
        int c = (idx & 15) << 2;
        size_t off = base + (size_t)r * HDIM + c;
        float4 kv = *(const float4*)&g_kh[off];
        Kt[c + 0][r] = kv.x; Kt[c + 1][r] = kv.y;
        Kt[c + 2][r] = kv.z; Kt[c + 3][r] = kv.w;
        *(float4*)&Vs[r][c] = *(const float4*)&g_vh[off];
    }

    // q row for this thread into registers (statically indexed)
    float qreg[64];
    {
        const float* qp = &g_qh[base + (size_t)t * HDIM];
#pragma unroll
        for (int d = 0; d < 64; d += 4) {
            float4 qv = *(const float4*)(qp + d);
            qreg[d] = qv.x; qreg[d + 1] = qv.y;
            qreg[d + 2] = qv.z; qreg[d + 3] = qv.w;
        }
    }
    __syncthreads();

    // scores: 32 packed pairs
    u64 s2[32];
#pragma unroll
    for (int j = 0; j < 32; j++) s2[j] = 0ULL;
#pragma unroll
    for (int d = 0; d < 64; d++) {
        u64 a2 = pack2(qreg[d], qreg[d]);
#pragma unroll
        for (int j = 0; j < 32; j++)
            ffma2(s2[j], a2, *(const u64*)&Kt[d][2 * j]);   // broadcast LDS.64
    }

    float s[64];
#pragma unroll
    for (int j = 0; j < 32; j++) unpack2(s2[j], s[2 * j], s[2 * j + 1]);

    // softmax (scale 1/sqrt(64) = 0.125)
    float m = -1e30f;
#pragma unroll
    for (int j = 0; j < 64; j++) { s[j] *= 0.125f; m = fmaxf(m, s[j]); }
    float sum = 0.f;
#pragma unroll
    for (int j = 0; j < 64; j++) { s[j] = __expf(s[j] - m); sum += s[j]; }
    float inv = 1.f / sum;
#pragma unroll
    for (int j = 0; j < 64; j++) s[j] *= inv;

    // top-5 values via branch-free cascade insertion: after the loop
    // v0 >= v1 >= v2 >= v3 >= v4 are the 5 largest entries (dups counted)
    float v0 = -1.f, v1 = -1.f, v2 = -1.f, v3 = -1.f, v4 = -1.f;
#pragma unroll
    for (int j = 0; j < 64; j++) {
        float x = s[j];
        float t0 = fmaxf(v0, x); x = fminf(v0, x); v0 = t0;
        float t1 = fmaxf(v1, x); x = fminf(v1, x); v1 = t1;
        float t2 = fmaxf(v2, x); x = fminf(v2, x); v2 = t2;
        float t3 = fmaxf(v3, x); x = fminf(v3, x); v3 = t3;
        v4 = fmaxf(v4, x);
    }
    float delta = v4 + 1e-7f;

    float wsum = 0.f;
#pragma unroll
    for (int j = 0; j < 64; j++) { s[j] = fmaxf(s[j] - delta, 0.f); wsum += s[j]; }
    float winv = 1.f / (wsum + 1e-7f);
#pragma unroll
    for (int j = 0; j < 64; j++) s[j] *= winv;

    // attn output in torch layout (h*B + b, q, k)
    float* ap = attn_out + (((size_t)h * BATCH + b) * 64 + t) * 64;
#pragma unroll
    for (int j = 0; j < 64; j += 4)
        *(float4*)(ap + j) = make_float4(s[j], s[j + 1], s[j + 2], s[j + 3]);

    // collect surviving (index, weight) pairs — mathematically <= 4, cap 6
    int   nzi[6];
    float nzw[6];
    int nnz = 0;
#pragma unroll
    for (int j = 0; j < 64; j++) {
        if (s[j] > 0.f && nnz < 6) { nzi[nnz] = j; nzw[nnz] = s[j]; nnz++; }
    }

    // sparse context = sum_{nz} w_j * V[j,:]
    u64 acc2v[32];
#pragma unroll
    for (int d2 = 0; d2 < 32; d2++) acc2v[d2] = 0ULL;
#pragma unroll 1
    for (int u = 0; u < nnz; u++) {
        int j = nzi[u];
        u64 w2 = pack2(nzw[u], nzw[u]);
#pragma unroll
        for (int d2 = 0; d2 < 32; d2++)
            ffma2(acc2v[d2], w2, *(const u64*)&Vs[j][2 * d2]);  // broadcast LDS.64
    }

    float* op = g_ctx + ((size_t)(b * 64 + t)) * HDIM + h * DK;
#pragma unroll
    for (int d2 = 0; d2 < 32; d2 += 2) {
        float c0, c1, c2, c3;
        unpack2(acc2v[d2], c0, c1);
        unpack2(acc2v[d2 + 1], c2, c3);
        *(float4*)(op + 2 * d2) = make_float4(c0, c1, c2, c3);
    }
}

// ---------------------------------------------------------------------------
// Kernel 3: fused gated output.
//   out[r,:] = sigmoid(ctx[r,:] @ gate_w^T + gate_b) * tanh(ctx[r,:] @ fc_w^T + fc_b)
// Tile 64x64, K-tile 32, 4x4 per thread per matrix via FFMA2, 256 threads.
// Software-pipelined (single buffer; barriers are <3% of iteration cost).
// grid = (256 row-tiles, 8 col-tiles)
// ---------------------------------------------------------------------------
__global__ __launch_bounds__(256) void fcgate_kernel(
    const float* __restrict__ fc_w, const float* __restrict__ fc_b,
    const float* __restrict__ gate_w, const float* __restrict__ gate_b,
    float* __restrict__ out, float* __restrict__ scalar_out)
{
    __shared__ float As[32][64];
    __shared__ float Fs[32][64];
    __shared__ float Gs[32][64];

    int tid = threadIdx.x;
    int m0 = blockIdx.x * 64;
    int n0 = blockIdx.y * 64;
    int arow = tid >> 2;           // 0..63
    int akk  = (tid & 3) << 2;     // 0,4,8,12 (second at +16)
    int tm = tid >> 4;             // 0..15
    int tn = tid & 15;             // 0..15

    const float* Ap = g_ctx  + (size_t)(m0 + arow) * HDIM + akk;
    const float* Fp = fc_w   + (size_t)(n0 + arow) * HDIM + akk;
    const float* Gp = gate_w + (size_t)(n0 + arow) * HDIM + akk;

    u64 acc2f[4][2], acc2g[4][2];
#pragma unroll
    for (int i = 0; i < 4; i++)
#pragma unroll
        for (int j = 0; j < 2; j++) { acc2f[i][j] = 0ULL; acc2g[i][j] = 0ULL; }

    float4 av0 = *(const float4*)(Ap);
    float4 av1 = *(const float4*)(Ap + 16);
    float4 fv0 = *(const float4*)(Fp);
    float4 fv1 = *(const float4*)(Fp + 16);
    float4 gv0 = *(const float4*)(Gp);
    float4 gv1 = *(const float4*)(Gp + 16);

    for (int k0 = 0; k0 < HDIM; k0 += 32) {
        __syncthreads();
        As[akk + 0][arow]  = av0.x; As[akk + 1][arow]  = av0.y;
        As[akk + 2][arow]  = av0.z; As[akk + 3][arow]  = av0.w;
        As[akk + 16][arow] = av1.x; As[akk + 17][arow] = av1.y;
        As[akk + 18][arow] = av1.z; As[akk + 19][arow] = av1.w;
        Fs[akk + 0][arow]  = fv0.x; Fs[akk + 1][arow]  = fv0.y;
        Fs[akk + 2][arow]  = fv0.z; Fs[akk + 3][arow]  = fv0.w;
        Fs[akk + 16][arow] = fv1.x; Fs[akk + 17][arow] = fv1.y;
        Fs[akk + 18][arow] = fv1.z; Fs[akk + 19][arow] = fv1.w;
        Gs[akk + 0][arow]  = gv0.x; Gs[akk + 1][arow]  = gv0.y;
        Gs[akk + 2][arow]  = gv0.z; Gs[akk + 3][arow]  = gv0.w;
        Gs[akk + 16][arow] = gv1.x; Gs[akk + 17][arow] = gv1.y;
        Gs[akk + 18][arow] = gv1.z; Gs[akk + 19][arow] = gv1.w;
        __syncthreads();

        // prefetch next tile before compute
        if (k0 + 32 < HDIM) {
            av0 = *(const float4*)(Ap + k0 + 32);
            av1 = *(const float4*)(Ap + k0 + 48);
            fv0 = *(const float4*)(Fp + k0 + 32);
            fv1 = *(const float4*)(Fp + k0 + 48);
            gv0 = *(const float4*)(Gp + k0 + 32);
            gv1 = *(const float4*)(Gp + k0 + 48);
        }

#pragma unroll
        for (int kk = 0; kk < 32; kk++) {
            float a[4];
            *(float4*)a = *(const float4*)&As[kk][tm * 4];
            u64 f2[2], g2[2];
            f2[0] = *(const u64*)&Fs[kk][tn * 4 + 0];   // pre-packed pairs
            f2[1] = *(const u64*)&Fs[kk][tn * 4 + 2];
            g2[0] = *(const u64*)&Gs[kk][tn * 4 + 0];
            g2[1] = *(const u64*)&Gs[kk][tn * 4 + 2];
#pragma unroll
            for (int i = 0; i < 4; i++) {
                u64 a2 = pack2(a[i], a[i]);
                ffma2(acc2f[i][0], a2, f2[0]);
                ffma2(acc2f[i][1], a2, f2[1]);
                ffma2(acc2g[i][0], a2, g2[0]);
                ffma2(acc2g[i][1], a2, g2[1]);
            }
        }
    }

#pragma unroll
    for (int i = 0; i < 4; i++) {
        int row = m0 + tm * 4 + i;
        float fv[4], gv[4], res[4];
        unpack2(acc2f[i][0], fv[0], fv[1]);
        unpack2(acc2f[i][1], fv[2], fv[3]);
        unpack2(acc2g[i][0], gv[0], gv[1]);
        unpack2(acc2g[i][1], gv[2], gv[3]);
#pragma unroll
        for (int j = 0; j < 4; j++) {
            int col = n0 + tn * 4 + j;
            float fval = fv[j] + fc_b[col];
            float gval = gv[j] + gate_b[col];
            float sg = 1.f / (1.f + __expf(-gval));
            res[j] = sg * tanhf(fval);
        }
        *(float4*)(out + (size_t)row * HDIM + n0 + tn * 4) =
            make_float4(res[0], res[1], res[2], res[3]);
    }

    if (blockIdx.x == 0 && blockIdx.y == 0 && tid == 0)
        *scalar_out = 0.f;   // third reference output (scalar 0.0)
}

// ---------------------------------------------------------------------------
extern "C" void kernel_launch(void* const* d_in, const int* in_sizes, int n_in,
                              void* d_out, int out_size)
{
    const float* q      = (const float*)d_in[0];
    const float* k      = (const float*)d_in[1];
    const float* v      = (const float*)d_in[2];
    const float* Wq     = (const float*)d_in[3];
    const float* Wk     = (const float*)d_in[4];
    const float* Wv     = (const float*)d_in[5];
    const float* fc_w   = (const float*)d_in[6];
    const float* fc_b   = (const float*)d_in[7];
    const float* gate_w = (const float*)d_in[8];
    const float* gate_b = (const float*)d_in[9];

    float* out  = (float*)d_out;
    float* attn = out + (size_t)BATCH * NBLK * DMODEL;      // second output
    float* scal = out + (size_t)out_size - 1;               // trailing scalar

    proj_kernel<<<dim3(4, 2, 192), 256>>>(q, k, v, Wq, Wk, Wv);
    attn_kernel<<<2048, 64>>>(attn);
    fcgate_kernel<<<dim3(256, 8), 256>>>(fc_w, fc_b, gate_w, gate_b, out, scal);
}

// round 14
// speedup vs baseline: 1.1363x; 1.1363x over previous
#include <cuda_runtime.h>
#include <math.h>

#define BATCH  256
#define NBLK   64
#define DMODEL 512
#define HDIM   512
#define NHEAD  8
#define DK     64

typedef unsigned long long u64;

union F4U2 { float4 f4; u64 d[2]; };

// Scratch (allocation-free rule: __device__ globals)
__device__ float g_qh[BATCH * NBLK * HDIM];
__device__ float g_kh[BATCH * NBLK * HDIM];
__device__ float g_vh[BATCH * NBLK * HDIM];
__device__ float g_ctx[BATCH * NBLK * HDIM];

// ---- packed fp32x2 helpers (sm_103a FFMA2 path) ----
__device__ __forceinline__ u64 pack2(float x, float y) {
    u64 r; asm("mov.b64 %0, {%1, %2};" : "=l"(r) : "f"(x), "f"(y)); return r;
}
__device__ __forceinline__ void unpack2(u64 v, float& x, float& y) {
    asm("mov.b64 {%0, %1}, %2;" : "=f"(x), "=f"(y) : "l"(v));
}
__device__ __forceinline__ void ffma2(u64& d, u64 a, u64 b) {
    asm("fma.rn.f32x2 %0, %1, %2, %3;" : "=l"(d) : "l"(a), "l"(b), "l"(d));
}

// ---------------------------------------------------------------------------
// Kernel 1: batched projections. 192 GEMMs, block tile 128x128, 128 threads,
// 8(M)x16(N) per thread via FFMA2. B-fragment columns spread as tn*4+32c so
// each quarter-warp phase covers all 32 banks exactly once (conflict-free).
// Double-buffered SMEM, one barrier per k-tile.
// grid = (4 ntiles, 2 mtiles, 192 g) with g = which*64 + n
// ---------------------------------------------------------------------------
__global__ __launch_bounds__(128) void proj_kernel(
    const float* __restrict__ q, const float* __restrict__ k, const float* __restrict__ v,
    const float* __restrict__ Wq, const float* __restrict__ Wk, const float* __restrict__ Wv)
{
    int g = blockIdx.z;
    int which = g >> 6;
    int n = g & 63;
    const float* A;
    const float* W;
    float* C;
    if (which == 0)      { A = q; W = Wq; C = g_qh; }
    else if (which == 1) { A = k; W = Wk; C = g_kh; }
    else                 { A = v; W = Wv; C = g_vh; }
    W += (size_t)n * DMODEL * HDIM;

    __shared__ float As[2][16][128];
    __shared__ float Bs[2][16][128];

    int tid  = threadIdx.x;       // 0..127
    int tm   = tid >> 3;          // 0..15 -> rows tm*8..+7
    int tn   = tid & 7;           // 0..7  -> cols tn*4 + 32c (c=0..3)
    int arow = tid;               // A loader: one row, full 16-k
    int brow = tid >> 5;          // 0..3  -> k rows brow+4w
    int bcol = (tid & 31) << 2;   // 0..124

    int m0 = blockIdx.y * 128;
    int n0 = blockIdx.x * 128;

    const float* Ap = A + ((size_t)(m0 + arow) * NBLK + n) * DMODEL;
    const float* Bp = W + (size_t)brow * HDIM + n0 + bcol;

    u64 acc2[8][8];
#pragma unroll
    for (int i = 0; i < 8; i++)
#pragma unroll
        for (int j = 0; j < 8; j++) acc2[i][j] = 0ULL;

    // prologue: tile 0 -> buffer 0
    {
        float4 a0 = *(const float4*)(Ap + 0);
        float4 a1 = *(const float4*)(Ap + 4);
        float4 a2_ = *(const float4*)(Ap + 8);
        float4 a3 = *(const float4*)(Ap + 12);
        As[0][0][arow]  = a0.x;  As[0][1][arow]  = a0.y;
        As[0][2][arow]  = a0.z;  As[0][3][arow]  = a0.w;
        As[0][4][arow]  = a1.x;  As[0][5][arow]  = a1.y;
        As[0][6][arow]  = a1.z;  As[0][7][arow]  = a1.w;
        As[0][8][arow]  = a2_.x; As[0][9][arow]  = a2_.y;
        As[0][10][arow] = a2_.z; As[0][11][arow] = a2_.w;
        As[0][12][arow] = a3.x;  As[0][13][arow] = a3.y;
        As[0][14][arow] = a3.z;  As[0][15][arow] = a3.w;
#pragma unroll
        for (int w = 0; w < 4; w++)
            *(float4*)&Bs[0][brow + 4 * w][bcol] =
                *(const float4*)(Bp + (size_t)(4 * w) * HDIM);
    }
    __syncthreads();

#pragma unroll 1
    for (int k0 = 0; k0 < DMODEL; k0 += 16) {
        int cur = (k0 >> 4) & 1;
        int nxt = cur ^ 1;
        bool have_next = (k0 + 16 < DMODEL);

        // next tile's global loads issued before compute (latency overlap)
        float4 a0, a1, a2_, a3, bv[4];
        if (have_next) {
            a0  = *(const float4*)(Ap + k0 + 16);
            a1  = *(const float4*)(Ap + k0 + 20);
            a2_ = *(const float4*)(Ap + k0 + 24);
            a3  = *(const float4*)(Ap + k0 + 28);
#pragma unroll
            for (int w = 0; w < 4; w++)
                bv[w] = *(const float4*)(Bp + (size_t)(k0 + 16 + 4 * w) * HDIM);
        }

#pragma unroll
        for (int kk = 0; kk < 16; kk++) {
            F4U2 fa0, fa1;
            fa0.f4 = *(const float4*)&As[cur][kk][tm * 8];
            fa1.f4 = *(const float4*)&As[cur][kk][tm * 8 + 4];
            u64 a2p[8];
            a2p[0] = pack2(fa0.f4.x, fa0.f4.x);
            a2p[1] = pack2(fa0.f4.y, fa0.f4.y);
            a2p[2] = pack2(fa0.f4.z, fa0.f4.z);
            a2p[3] = pack2(fa0.f4.w, fa0.f4.w);
            a2p[4] = pack2(fa1.f4.x, fa1.f4.x);
            a2p[5] = pack2(fa1.f4.y, fa1.f4.y);
            a2p[6] = pack2(fa1.f4.z, fa1.f4.z);
            a2p[7] = pack2(fa1.f4.w, fa1.f4.w);
            F4U2 fb[4];
#pragma unroll
            for (int c = 0; c < 4; c++)
                fb[c].f4 = *(const float4*)&Bs[cur][kk][tn * 4 + 32 * c];
#pragma unroll
            for (int i = 0; i < 8; i++)
#pragma unroll
                for (int c = 0; c < 4; c++) {
                    ffma2(acc2[i][2 * c],     a2p[i], fb[c].d[0]);
                    ffma2(acc2[i][2 * c + 1], a2p[i], fb[c].d[1]);
                }
        }

        if (have_next) {
            As[nxt][0][arow]  = a0.x;  As[nxt][1][arow]  = a0.y;
            As[nxt][2][arow]  = a0.z;  As[nxt][3][arow]  = a0.w;
            As[nxt][4][arow]  = a1.x;  As[nxt][5][arow]  = a1.y;
            As[nxt][6][arow]  = a1.z;  As[nxt][7][arow]  = a1.w;
            As[nxt][8][arow]  = a2_.x; As[nxt][9][arow]  = a2_.y;
            As[nxt][10][arow] = a2_.z; As[nxt][11][arow] = a2_.w;
            As[nxt][12][arow] = a3.x;  As[nxt][13][arow] = a3.y;
            As[nxt][14][arow] = a3.z;  As[nxt][15][arow] = a3.w;
#pragma unroll
            for (int w = 0; w < 4; w++)
                *(float4*)&Bs[nxt][brow + 4 * w][bcol] = bv[w];
            __syncthreads();   // one barrier per k-tile
        }
    }

#pragma unroll
    for (int i = 0; i < 8; i++) {
        size_t row = (size_t)(m0 + tm * 8 + i);
        float* Cp = C + (row * NBLK + n) * HDIM + n0 + tn * 4;
#pragma unroll
        for (int c = 0; c < 4; c++) {
            F4U2 o;
            o.d[0] = acc2[i][2 * c];
            o.d[1] = acc2[i][2 * c + 1];
            *(float4*)(Cp + 32 * c) = o.f4;
        }
    }
}

// ---------------------------------------------------------------------------
// Kernel 2: attention per (b,h). 2048 blocks x 64 threads.
// S = QK^T/8 -> softmax -> top5 sparsify + renorm -> write attn + sparse P*V.
// ---------------------------------------------------------------------------
__global__ __launch_bounds__(64) void attn_kernel(float* __restrict__ attn_out)
{
    int bh = blockIdx.x;
    int b = bh >> 3;
    int h = bh & 7;

    __shared__ float Kt[64][66];   // transposed K; stride 66 keeps u64 loads aligned
    __shared__ float Vs[64][64];

    int t = threadIdx.x;
    size_t base = (size_t)b * 64 * HDIM + h * DK;

    for (int idx = t; idx < 64 * 16; idx += 64) {
        int r = idx >> 4;
        int c = (idx & 15) << 2;
        size_t off = base + (size_t)r * HDIM + c;
        float4 kv = *(const float4*)&g_kh[off];
        Kt[c + 0][r] = kv.x; Kt[c + 1][r] = kv.y;
        Kt[c + 2][r] = kv.z; Kt[c + 3][r] = kv.w;
        *(float4*)&Vs[r][c] = *(const float4*)&g_vh[off];
    }

    float qreg[64];
    {
        const float* qp = &g_qh[base + (size_t)t * HDIM];
#pragma unroll
        for (int d = 0; d < 64; d += 4) {
            float4 qv = *(const float4*)(qp + d);
            qreg[d] = qv.x; qreg[d + 1] = qv.y;
            qreg[d + 2] = qv.z; qreg[d + 3] = qv.w;
        }
    }
    __syncthreads();

    u64 s2[32];
#pragma unroll
    for (int j = 0; j < 32; j++) s2[j] = 0ULL;
#pragma unroll
    for (int d = 0; d < 64; d++) {
        u64 a2 = pack2(qreg[d], qreg[d]);
#pragma unroll
        for (int j = 0; j < 32; j++)
            ffma2(s2[j], a2, *(const u64*)&Kt[d][2 * j]);   // broadcast LDS.64
    }

    float s[64];
#pragma unroll
    for (int j = 0; j < 32; j++) unpack2(s2[j], s[2 * j], s[2 * j + 1]);

    // softmax (scale 1/sqrt(64) = 0.125)
    float m = -1e30f;
#pragma unroll
    for (int j = 0; j < 64; j++) { s[j] *= 0.125f; m = fmaxf(m, s[j]); }
    float sum = 0.f;
#pragma unroll
    for (int j = 0; j < 64; j++) { s[j] = __expf(s[j] - m); sum += s[j]; }
    float inv = 1.f / sum;
#pragma unroll
    for (int j = 0; j < 64; j++) s[j] *= inv;

    // top-5 via branch-free cascade insertion (v4 = 5th largest, dups counted)
    float v0 = -1.f, v1 = -1.f, v2 = -1.f, v3 = -1.f, v4 = -1.f;
#pragma unroll
    for (int j = 0; j < 64; j++) {
        float x = s[j];
        float t0 = fmaxf(v0, x); x = fminf(v0, x); v0 = t0;
        float t1 = fmaxf(v1, x); x = fminf(v1, x); v1 = t1;
        float t2 = fmaxf(v2, x); x = fminf(v2, x); v2 = t2;
        float t3 = fmaxf(v3, x); x = fminf(v3, x); v3 = t3;
        v4 = fmaxf(v4, x);
    }
    float delta = v4 + 1e-7f;

    float wsum = 0.f;
#pragma unroll
    for (int j = 0; j < 64; j++) { s[j] = fmaxf(s[j] - delta, 0.f); wsum += s[j]; }
    float winv = 1.f / (wsum + 1e-7f);
#pragma unroll
    for (int j = 0; j < 64; j++) s[j] *= winv;

    // attn output in torch layout (h*B + b, q, k)
    float* ap = attn_out + (((size_t)h * BATCH + b) * 64 + t) * 64;
#pragma unroll
    for (int j = 0; j < 64; j += 4)
        *(float4*)(ap + j) = make_float4(s[j], s[j + 1], s[j + 2], s[j + 3]);

    // collect surviving (index, weight) pairs — mathematically <= 4, cap 6
    int   nzi[6];
    float nzw[6];
    int nnz = 0;
#pragma unroll
    for (int j = 0; j < 64; j++) {
        if (s[j] > 0.f && nnz < 6) { nzi[nnz] = j; nzw[nnz] = s[j]; nnz++; }
    }

    u64 acc2v[32];
#pragma unroll
    for (int d2 = 0; d2 < 32; d2++) acc2v[d2] = 0ULL;
#pragma unroll 1
    for (int u = 0; u < nnz; u++) {
        int j = nzi[u];
        u64 w2 = pack2(nzw[u], nzw[u]);
#pragma unroll
        for (int d2 = 0; d2 < 32; d2++)
            ffma2(acc2v[d2], w2, *(const u64*)&Vs[j][2 * d2]);  // broadcast LDS.64
    }

    float* op = g_ctx + ((size_t)(b * 64 + t)) * HDIM + h * DK;
#pragma unroll
    for (int d2 = 0; d2 < 32; d2 += 2) {
        float c0, c1, c2, c3;
        unpack2(acc2v[d2], c0, c1);
        unpack2(acc2v[d2 + 1], c2, c3);
        *(float4*)(op + 2 * d2) = make_float4(c0, c1, c2, c3);
    }
}

// ---------------------------------------------------------------------------
// Kernel 3: fused gated output. Block tile 128(M)x64(N), 256 threads,
// 8(M)x4(N) per thread for BOTH matrices (64 B smem per 128 FMA).
// grid = (128 row-tiles, 8 col-tiles)
// ---------------------------------------------------------------------------
__global__ __launch_bounds__(256) void fcgate_kernel(
    const float* __restrict__ fc_w, const float* __restrict__ fc_b,
    const float* __restrict__ gate_w, const float* __restrict__ gate_b,
    float* __restrict__ out, float* __restrict__ scalar_out)
{
    __shared__ float As[32][128];
    __shared__ float Fs[32][64];
    __shared__ float Gs[32][64];

    int tid = threadIdx.x;
    int m0 = blockIdx.x * 128;
    int n0 = blockIdx.y * 64;
    int tm = tid >> 4;             // 0..15 -> rows tm*8..+7
    int tn = tid & 15;             // 0..15 -> cols tn*4..+3
    // A loader: 128 rows x 32 k -> 4 float4/thread
    int arow = tid >> 1;           // 0..127
    int akk  = (tid & 1) << 2;     // 0 or 4; chunks at akk + 8w
    // F/G loader: 64 cols x 32 k -> 2 float4/thread each
    int frow = tid >> 2;           // 0..63 (column index)
    int fkk  = (tid & 3) << 2;     // 0,4,8,12; chunks at fkk, fkk+16

    const float* Ap = g_ctx  + (size_t)(m0 + arow) * HDIM + akk;
    const float* Fp = fc_w   + (size_t)(n0 + frow) * HDIM + fkk;
    const float* Gp = gate_w + (size_t)(n0 + frow) * HDIM + fkk;

    u64 acc2f[8][2], acc2g[8][2];
#pragma unroll
    for (int i = 0; i < 8; i++) {
        acc2f[i][0] = 0ULL; acc2f[i][1] = 0ULL;
        acc2g[i][0] = 0ULL; acc2g[i][1] = 0ULL;
    }

    float4 av[4], fv[2], gv[2];
#pragma unroll
    for (int w = 0; w < 4; w++) av[w] = *(const float4*)(Ap + 8 * w);
    fv[0] = *(const float4*)(Fp);      fv[1] = *(const float4*)(Fp + 16);
    gv[0] = *(const float4*)(Gp);      gv[1] = *(const float4*)(Gp + 16);

#pragma unroll 1
    for (int k0 = 0; k0 < HDIM; k0 += 32) {
        __syncthreads();
#pragma unroll
        for (int w = 0; w < 4; w++) {
            As[akk + 8 * w + 0][arow] = av[w].x;
            As[akk + 8 * w + 1][arow] = av[w].y;
            As[akk + 8 * w + 2][arow] = av[w].z;
            As[akk + 8 * w + 3][arow] = av[w].w;
        }
        Fs[fkk + 0][frow]  = fv[0].x; Fs[fkk + 1][frow]  = fv[0].y;
        Fs[fkk + 2][frow]  = fv[0].z; Fs[fkk + 3][frow]  = fv[0].w;
        Fs[fkk + 16][frow] = fv[1].x; Fs[fkk + 17][frow] = fv[1].y;
        Fs[fkk + 18][frow] = fv[1].z; Fs[fkk + 19][frow] = fv[1].w;
        Gs[fkk + 0][frow]  = gv[0].x; Gs[fkk + 1][frow]  = gv[0].y;
        Gs[fkk + 2][frow]  = gv[0].z; Gs[fkk + 3][frow]  = gv[0].w;
        Gs[fkk + 16][frow] = gv[1].x; Gs[fkk + 17][frow] = gv[1].y;
        Gs[fkk + 18][frow] = gv[1].z; Gs[fkk + 19][frow] = gv[1].w;
        __syncthreads();

        if (k0 + 32 < HDIM) {
#pragma unroll
            for (int w = 0; w < 4; w++)
                av[w] = *(const float4*)(Ap + k0 + 32 + 8 * w);
            fv[0] = *(const float4*)(Fp + k0 + 32);
            fv[1] = *(const float4*)(Fp + k0 + 48);
            gv[0] = *(const float4*)(Gp + k0 + 32);
            gv[1] = *(const float4*)(Gp + k0 + 48);
        }

#pragma unroll
        for (int kk = 0; kk < 32; kk++) {
            F4U2 fa0, fa1;
            fa0.f4 = *(const float4*)&As[kk][tm * 8];
            fa1.f4 = *(const float4*)&As[kk][tm * 8 + 4];
            u64 a2p[8];
            a2p[0] = pack2(fa0.f4.x, fa0.f4.x);
            a2p[1] = pack2(fa0.f4.y, fa0.f4.y);
            a2p[2] = pack2(fa0.f4.z, fa0.f4.z);
            a2p[3] = pack2(fa0.f4.w, fa0.f4.w);
            a2p[4] = pack2(fa1.f4.x, fa1.f4.x);
            a2p[5] = pack2(fa1.f4.y, fa1.f4.y);
            a2p[6] = pack2(fa1.f4.z, fa1.f4.z);
            a2p[7] = pack2(fa1.f4.w, fa1.f4.w);
            F4U2 ff, fg;
            ff.f4 = *(const float4*)&Fs[kk][tn * 4];
            fg.f4 = *(const float4*)&Gs[kk][tn * 4];
#pragma unroll
            for (int i = 0; i < 8; i++) {
                ffma2(acc2f[i][0], a2p[i], ff.d[0]);
                ffma2(acc2f[i][1], a2p[i], ff.d[1]);
                ffma2(acc2g[i][0], a2p[i], fg.d[0]);
                ffma2(acc2g[i][1], a2p[i], fg.d[1]);
            }
        }
    }

#pragma unroll
    for (int i = 0; i < 8; i++) {
        int row = m0 + tm * 8 + i;
        float fvv[4], gvv[4], res[4];
        unpack2(acc2f[i][0], fvv[0], fvv[1]);
        unpack2(acc2f[i][1], fvv[2], fvv[3]);
        unpack2(acc2g[i][0], gvv[0], gvv[1]);
        unpack2(acc2g[i][1], gvv[2], gvv[3]);
#pragma unroll
        for (int j = 0; j < 4; j++) {
            int col = n0 + tn * 4 + j;
            float fval = fvv[j] + fc_b[col];
            float gval = gvv[j] + gate_b[col];
            float sg = 1.f / (1.f + __expf(-gval));
            res[j] = sg * tanhf(fval);
        }
        *(float4*)(out + (size_t)row * HDIM + n0 + tn * 4) =
            make_float4(res[0], res[1], res[2], res[3]);
    }

    if (blockIdx.x == 0 && blockIdx.y == 0 && tid == 0)
        *scalar_out = 0.f;   // third reference output (scalar 0.0)
}

// ---------------------------------------------------------------------------
extern "C" void kernel_launch(void* const* d_in, const int* in_sizes, int n_in,
                              void* d_out, int out_size)
{
    const float* q      = (const float*)d_in[0];
    const float* k      = (const float*)d_in[1];
    const float* v      = (const float*)d_in[2];
    const float* Wq     = (const float*)d_in[3];
    const float* Wk     = (const float*)d_in[4];
    const float* Wv     = (const float*)d_in[5];
    const float* fc_w   = (const float*)d_in[6];
    const float* fc_b   = (const float*)d_in[7];
    const float* gate_w = (const float*)d_in[8];
    const float* gate_b = (const float*)d_in[9];

    float* out  = (float*)d_out;
    float* attn = out + (size_t)BATCH * NBLK * DMODEL;      // second output
    float* scal = out + (size_t)out_size - 1;               // trailing scalar

    proj_kernel<<<dim3(4, 2, 192), 128>>>(q, k, v, Wq, Wk, Wv);
    attn_kernel<<<2048, 64>>>(attn);
    fcgate_kernel<<<dim3(128, 8), 256>>>(fc_w, fc_b, gate_w, gate_b, out, scal);
}

// round 17
// speedup vs baseline: 1.1628x; 1.0233x over previous
#include <cuda_runtime.h>
#include <math.h>

#define BATCH  256
#define NBLK   64
#define DMODEL 512
#define HDIM   512
#define NHEAD  8
#define DK     64

typedef unsigned long long u64;

union F4U2 { float4 f4; u64 d[2]; };

// Scratch (allocation-free rule: __device__ globals)
__device__ float g_qh[BATCH * NBLK * HDIM];
__device__ float g_kh[BATCH * NBLK * HDIM];
__device__ float g_vh[BATCH * NBLK * HDIM];
__device__ float g_ctx[BATCH * NBLK * HDIM];

// ---- packed fp32x2 helpers (sm_103a FFMA2 path) ----
__device__ __forceinline__ u64 pack2(float x, float y) {
    u64 r; asm("mov.b64 %0, {%1, %2};" : "=l"(r) : "f"(x), "f"(y)); return r;
}
__device__ __forceinline__ void unpack2(u64 v, float& x, float& y) {
    asm("mov.b64 {%0, %1}, %2;" : "=f"(x), "=f"(y) : "l"(v));
}
__device__ __forceinline__ void ffma2(u64& d, u64 a, u64 b) {
    asm("fma.rn.f32x2 %0, %1, %2, %3;" : "=l"(d) : "l"(a), "l"(b), "l"(d));
}

// ---------------------------------------------------------------------------
// Kernel 1: batched projections. 192 GEMMs, block tile 128x128, 256 threads,
// 8(M)x8(N) per thread via FFMA2. B-fragment columns at tn*4 and tn*4+64:
// each 8-lane phase covers all 32 banks exactly once (conflict-free).
// Double-buffered SMEM (one barrier per k-tile); 2 CTA/SM via launch_bounds.
// grid = (4 ntiles, 2 mtiles, 192 g) with g = which*64 + n
// ---------------------------------------------------------------------------
__global__ __launch_bounds__(256, 2) void proj_kernel(
    const float* __restrict__ q, const float* __restrict__ k, const float* __restrict__ v,
    const float* __restrict__ Wq, const float* __restrict__ Wk, const float* __restrict__ Wv)
{
    int g = blockIdx.z;
    int which = g >> 6;
    int n = g & 63;
    const float* A;
    const float* W;
    float* C;
    if (which == 0)      { A = q; W = Wq; C = g_qh; }
    else if (which == 1) { A = k; W = Wk; C = g_kh; }
    else                 { A = v; W = Wv; C = g_vh; }
    W += (size_t)n * DMODEL * HDIM;

    __shared__ float As[2][16][128];
    __shared__ float Bs[2][16][128];

    int tid  = threadIdx.x;       // 0..255
    int tm   = tid >> 4;          // 0..15 -> rows tm*8..+7
    int tn   = tid & 15;          // 0..15 -> cols tn*4 and tn*4+64
    int arow = tid >> 1;          // 0..127
    int akk  = (tid & 1) << 2;    // 0 or 4 (second chunk at +8)
    int brow = tid >> 5;          // 0..7   (second at +8)
    int bcol = (tid & 31) << 2;   // 0..124

    int m0 = blockIdx.y * 128;
    int n0 = blockIdx.x * 128;

    const float* Ap = A + ((size_t)(m0 + arow) * NBLK + n) * DMODEL + akk;
    const float* Bp = W + (size_t)brow * HDIM + n0 + bcol;

    u64 acc2[8][4];
#pragma unroll
    for (int i = 0; i < 8; i++)
#pragma unroll
        for (int j = 0; j < 4; j++) acc2[i][j] = 0ULL;

    // prologue: tile 0 -> buffer 0
    {
        float4 av0 = *(const float4*)(Ap);
        float4 av1 = *(const float4*)(Ap + 8);
        float4 bv0 = *(const float4*)(Bp);
        float4 bv1 = *(const float4*)(Bp + (size_t)8 * HDIM);
        As[0][akk + 0][arow]  = av0.x;
        As[0][akk + 1][arow]  = av0.y;
        As[0][akk + 2][arow]  = av0.z;
        As[0][akk + 3][arow]  = av0.w;
        As[0][akk + 8][arow]  = av1.x;
        As[0][akk + 9][arow]  = av1.y;
        As[0][akk + 10][arow] = av1.z;
        As[0][akk + 11][arow] = av1.w;
        *(float4*)&Bs[0][brow][bcol]     = bv0;
        *(float4*)&Bs[0][brow + 8][bcol] = bv1;
    }
    __syncthreads();

#pragma unroll 1
    for (int k0 = 0; k0 < DMODEL; k0 += 16) {
        int cur = (k0 >> 4) & 1;
        int nxt = cur ^ 1;
        bool have_next = (k0 + 16 < DMODEL);

        // next tile's global loads issued before compute (latency overlap)
        float4 av0, av1, bv0, bv1;
        if (have_next) {
            av0 = *(const float4*)(Ap + k0 + 16);
            av1 = *(const float4*)(Ap + k0 + 24);
            bv0 = *(const float4*)(Bp + (size_t)(k0 + 16) * HDIM);
            bv1 = *(const float4*)(Bp + (size_t)(k0 + 24) * HDIM);
        }

#pragma unroll
        for (int kk = 0; kk < 16; kk++) {
            F4U2 fa0, fa1;
            fa0.f4 = *(const float4*)&As[cur][kk][tm * 8];       // broadcast
            fa1.f4 = *(const float4*)&As[cur][kk][tm * 8 + 4];
            F4U2 fb0, fb1;
            fb0.f4 = *(const float4*)&Bs[cur][kk][tn * 4];       // conflict-free
            fb1.f4 = *(const float4*)&Bs[cur][kk][tn * 4 + 64];
            u64 a2p[8];
            a2p[0] = pack2(fa0.f4.x, fa0.f4.x);
            a2p[1] = pack2(fa0.f4.y, fa0.f4.y);
            a2p[2] = pack2(fa0.f4.z, fa0.f4.z);
            a2p[3] = pack2(fa0.f4.w, fa0.f4.w);
            a2p[4] = pack2(fa1.f4.x, fa1.f4.x);
            a2p[5] = pack2(fa1.f4.y, fa1.f4.y);
            a2p[6] = pack2(fa1.f4.z, fa1.f4.z);
            a2p[7] = pack2(fa1.f4.w, fa1.f4.w);
#pragma unroll
            for (int i = 0; i < 8; i++) {
                ffma2(acc2[i][0], a2p[i], fb0.d[0]);
                ffma2(acc2[i][1], a2p[i], fb0.d[1]);
                ffma2(acc2[i][2], a2p[i], fb1.d[0]);
                ffma2(acc2[i][3], a2p[i], fb1.d[1]);
            }
        }

        if (have_next) {
            As[nxt][akk + 0][arow]  = av0.x;
            As[nxt][akk + 1][arow]  = av0.y;
            As[nxt][akk + 2][arow]  = av0.z;
            As[nxt][akk + 3][arow]  = av0.w;
            As[nxt][akk + 8][arow]  = av1.x;
            As[nxt][akk + 9][arow]  = av1.y;
            As[nxt][akk + 10][arow] = av1.z;
            As[nxt][akk + 11][arow] = av1.w;
            *(float4*)&Bs[nxt][brow][bcol]     = bv0;
            *(float4*)&Bs[nxt][brow + 8][bcol] = bv1;
            __syncthreads();   // one barrier per k-tile
        }
    }

#pragma unroll
    for (int i = 0; i < 8; i++) {
        size_t row = (size_t)(m0 + tm * 8 + i);
        float* Cp = C + (row * NBLK + n) * HDIM + n0 + tn * 4;
        F4U2 o0, o1;
        o0.d[0] = acc2[i][0]; o0.d[1] = acc2[i][1];
        o1.d[0] = acc2[i][2]; o1.d[1] = acc2[i][3];
        *(float4*)Cp        = o0.f4;
        *(float4*)(Cp + 64) = o1.f4;
    }
}

// ---------------------------------------------------------------------------
// Kernel 2: attention per (b,h). 2048 blocks x 64 threads.
// S = QK^T/8 -> softmax -> top5 sparsify + renorm -> write attn + sparse P*V.
// ---------------------------------------------------------------------------
__global__ __launch_bounds__(64) void attn_kernel(float* __restrict__ attn_out)
{
    int bh = blockIdx.x;
    int b = bh >> 3;
    int h = bh & 7;

    __shared__ float Kt[64][66];   // transposed K; stride 66 keeps u64 loads aligned
    __shared__ float Vs[64][64];

    int t = threadIdx.x;
    size_t base = (size_t)b * 64 * HDIM + h * DK;

    for (int idx = t; idx < 64 * 16; idx += 64) {
        int r = idx >> 4;
        int c = (idx & 15) << 2;
        size_t off = base + (size_t)r * HDIM + c;
        float4 kv = *(const float4*)&g_kh[off];
        Kt[c + 0][r] = kv.x; Kt[c + 1][r] = kv.y;
        Kt[c + 2][r] = kv.z; Kt[c + 3][r] = kv.w;
        *(float4*)&Vs[r][c] = *(const float4*)&g_vh[off];
    }

    float qreg[64];
    {
        const float* qp = &g_qh[base + (size_t)t * HDIM];
#pragma unroll
        for (int d = 0; d < 64; d += 4) {
            float4 qv = *(const float4*)(qp + d);
            qreg[d] = qv.x; qreg[d + 1] = qv.y;
            qreg[d + 2] = qv.z; qreg[d + 3] = qv.w;
        }
    }
    __syncthreads();

    u64 s2[32];
#pragma unroll
    for (int j = 0; j < 32; j++) s2[j] = 0ULL;
#pragma unroll
    for (int d = 0; d < 64; d++) {
        u64 a2 = pack2(qreg[d], qreg[d]);
#pragma unroll
        for (int j = 0; j < 32; j++)
            ffma2(s2[j], a2, *(const u64*)&Kt[d][2 * j]);   // broadcast LDS.64
    }

    float s[64];
#pragma unroll
    for (int j = 0; j < 32; j++) unpack2(s2[j], s[2 * j], s[2 * j + 1]);

    // softmax (scale 1/sqrt(64) = 0.125)
    float m = -1e30f;
#pragma unroll
    for (int j = 0; j < 64; j++) { s[j] *= 0.125f; m = fmaxf(m, s[j]); }
    float sum = 0.f;
#pragma unroll
    for (int j = 0; j < 64; j++) { s[j] = __expf(s[j] - m); sum += s[j]; }
    float inv = 1.f / sum;
#pragma unroll
    for (int j = 0; j < 64; j++) s[j] *= inv;

    // top-5 via branch-free cascade insertion (v4 = 5th largest, dups counted)
    float v0 = -1.f, v1 = -1.f, v2 = -1.f, v3 = -1.f, v4 = -1.f;
#pragma unroll
    for (int j = 0; j < 64; j++) {
        float x = s[j];
        float t0 = fmaxf(v0, x); x = fminf(v0, x); v0 = t0;
        float t1 = fmaxf(v1, x); x = fminf(v1, x); v1 = t1;
        float t2 = fmaxf(v2, x); x = fminf(v2, x); v2 = t2;
        float t3 = fmaxf(v3, x); x = fminf(v3, x); v3 = t3;
        v4 = fmaxf(v4, x);
    }
    float delta = v4 + 1e-7f;

    float wsum = 0.f;
#pragma unroll
    for (int j = 0; j < 64; j++) { s[j] = fmaxf(s[j] - delta, 0.f); wsum += s[j]; }
    float winv = 1.f / (wsum + 1e-7f);
#pragma unroll
    for (int j = 0; j < 64; j++) s[j] *= winv;

    // attn output in torch layout (h*B + b, q, k)
    float* ap = attn_out + (((size_t)h * BATCH + b) * 64 + t) * 64;
#pragma unroll
    for (int j = 0; j < 64; j += 4)
        *(float4*)(ap + j) = make_float4(s[j], s[j + 1], s[j + 2], s[j + 3]);

    // collect surviving (index, weight) pairs — mathematically <= 4, cap 6
    int   nzi[6];
    float nzw[6];
    int nnz = 0;
#pragma unroll
    for (int j = 0; j < 64; j++) {
        if (s[j] > 0.f && nnz < 6) { nzi[nnz] = j; nzw[nnz] = s[j]; nnz++; }
    }

    u64 acc2v[32];
#pragma unroll
    for (int d2 = 0; d2 < 32; d2++) acc2v[d2] = 0ULL;
#pragma unroll 1
    for (int u = 0; u < nnz; u++) {
        int j = nzi[u];
        u64 w2 = pack2(nzw[u], nzw[u]);
#pragma unroll
        for (int d2 = 0; d2 < 32; d2++)
            ffma2(acc2v[d2], w2, *(const u64*)&Vs[j][2 * d2]);  // broadcast LDS.64
    }

    float* op = g_ctx + ((size_t)(b * 64 + t)) * HDIM + h * DK;
#pragma unroll
    for (int d2 = 0; d2 < 32; d2 += 2) {
        float c0, c1, c2, c3;
        unpack2(acc2v[d2], c0, c1);
        unpack2(acc2v[d2 + 1], c2, c3);
        *(float4*)(op + 2 * d2) = make_float4(c0, c1, c2, c3);
    }
}

// ---------------------------------------------------------------------------
// Kernel 3: fused gated output. Block tile 128(M)x64(N), 256 threads,
// 8(M)x4(N) per thread for BOTH matrices (64 B smem per 128 FMA).
// grid = (128 row-tiles, 8 col-tiles)
// ---------------------------------------------------------------------------
__global__ __launch_bounds__(256) void fcgate_kernel(
    const float* __restrict__ fc_w, const float* __restrict__ fc_b,
    const float* __restrict__ gate_w, const float* __restrict__ gate_b,
    float* __restrict__ out, float* __restrict__ scalar_out)
{
    __shared__ float As[32][128];
    __shared__ float Fs[32][64];
    __shared__ float Gs[32][64];

    int tid = threadIdx.x;
    int m0 = blockIdx.x * 128;
    int n0 = blockIdx.y * 64;
    int tm = tid >> 4;             // 0..15 -> rows tm*8..+7
    int tn = tid & 15;             // 0..15 -> cols tn*4..+3
    // A loader: 128 rows x 32 k -> 4 float4/thread
    int arow = tid >> 1;           // 0..127
    int akk  = (tid & 1) << 2;     // 0 or 4; chunks at akk + 8w
    // F/G loader: 64 cols x 32 k -> 2 float4/thread each
    int frow = tid >> 2;           // 0..63 (column index)
    int fkk  = (tid & 3) << 2;     // 0,4,8,12; chunks at fkk, fkk+16

    const float* Ap = g_ctx  + (size_t)(m0 + arow) * HDIM + akk;
    const float* Fp = fc_w   + (size_t)(n0 + frow) * HDIM + fkk;
    const float* Gp = gate_w + (size_t)(n0 + frow) * HDIM + fkk;

    u64 acc2f[8][2], acc2g[8][2];
#pragma unroll
    for (int i = 0; i < 8; i++) {
        acc2f[i][0] = 0ULL; acc2f[i][1] = 0ULL;
        acc2g[i][0] = 0ULL; acc2g[i][1] = 0ULL;
    }

    float4 av[4], fv[2], gv[2];
#pragma unroll
    for (int w = 0; w < 4; w++) av[w] = *(const float4*)(Ap + 8 * w);
    fv[0] = *(const float4*)(Fp);      fv[1] = *(const float4*)(Fp + 16);
    gv[0] = *(const float4*)(Gp);      gv[1] = *(const float4*)(Gp + 16);

#pragma unroll 1
    for (int k0 = 0; k0 < HDIM; k0 += 32) {
        __syncthreads();
#pragma unroll
        for (int w = 0; w < 4; w++) {
            As[akk + 8 * w + 0][arow] = av[w].x;
            As[akk + 8 * w + 1][arow] = av[w].y;
            As[akk + 8 * w + 2][arow] = av[w].z;
            As[akk + 8 * w + 3][arow] = av[w].w;
        }
        Fs[fkk + 0][frow]  = fv[0].x; Fs[fkk + 1][frow]  = fv[0].y;
        Fs[fkk + 2][frow]  = fv[0].z; Fs[fkk + 3][frow]  = fv[0].w;
        Fs[fkk + 16][frow] = fv[1].x; Fs[fkk + 17][frow] = fv[1].y;
        Fs[fkk + 18][frow] = fv[1].z; Fs[fkk + 19][frow] = fv[1].w;
        Gs[fkk + 0][frow]  = gv[0].x; Gs[fkk + 1][frow]  = gv[0].y;
        Gs[fkk + 2][frow]  = gv[0].z; Gs[fkk + 3][frow]  = gv[0].w;
        Gs[fkk + 16][frow] = gv[1].x; Gs[fkk + 17][frow] = gv[1].y;
        Gs[fkk + 18][frow] = gv[1].z; Gs[fkk + 19][frow] = gv[1].w;
        __syncthreads();

        if (k0 + 32 < HDIM) {
#pragma unroll
            for (int w = 0; w < 4; w++)
                av[w] = *(const float4*)(Ap + k0 + 32 + 8 * w);
            fv[0] = *(const float4*)(Fp + k0 + 32);
            fv[1] = *(const float4*)(Fp + k0 + 48);
            gv[0] = *(const float4*)(Gp + k0 + 32);
            gv[1] = *(const float4*)(Gp + k0 + 48);
        }

#pragma unroll
        for (int kk = 0; kk < 32; kk++) {
            F4U2 fa0, fa1;
            fa0.f4 = *(const float4*)&As[kk][tm * 8];
            fa1.f4 = *(const float4*)&As[kk][tm * 8 + 4];
            u64 a2p[8];
            a2p[0] = pack2(fa0.f4.x, fa0.f4.x);
            a2p[1] = pack2(fa0.f4.y, fa0.f4.y);
            a2p[2] = pack2(fa0.f4.z, fa0.f4.z);
            a2p[3] = pack2(fa0.f4.w, fa0.f4.w);
            a2p[4] = pack2(fa1.f4.x, fa1.f4.x);
            a2p[5] = pack2(fa1.f4.y, fa1.f4.y);
            a2p[6] = pack2(fa1.f4.z, fa1.f4.z);
            a2p[7] = pack2(fa1.f4.w, fa1.f4.w);
            F4U2 ff, fg;
            ff.f4 = *(const float4*)&Fs[kk][tn * 4];
            fg.f4 = *(const float4*)&Gs[kk][tn * 4];
#pragma unroll
            for (int i = 0; i < 8; i++) {
                ffma2(acc2f[i][0], a2p[i], ff.d[0]);
                ffma2(acc2f[i][1], a2p[i], ff.d[1]);
                ffma2(acc2g[i][0], a2p[i], fg.d[0]);
                ffma2(acc2g[i][1], a2p[i], fg.d[1]);
            }
        }
    }

#pragma unroll
    for (int i = 0; i < 8; i++) {
        int row = m0 + tm * 8 + i;
        float fvv[4], gvv[4], res[4];
        unpack2(acc2f[i][0], fvv[0], fvv[1]);
        unpack2(acc2f[i][1], fvv[2], fvv[3]);
        unpack2(acc2g[i][0], gvv[0], gvv[1]);
        unpack2(acc2g[i][1], gvv[2], gvv[3]);
#pragma unroll
        for (int j = 0; j < 4; j++) {
            int col = n0 + tn * 4 + j;
            float fval = fvv[j] + fc_b[col];
            float gval = gvv[j] + gate_b[col];
            float sg = 1.f / (1.f + __expf(-gval));
            res[j] = sg * tanhf(fval);
        }
        *(float4*)(out + (size_t)row * HDIM + n0 + tn * 4) =
            make_float4(res[0], res[1], res[2], res[3]);
    }

    if (blockIdx.x == 0 && blockIdx.y == 0 && tid == 0)
        *scalar_out = 0.f;   // third reference output (scalar 0.0)
}

// ---------------------------------------------------------------------------
extern "C" void kernel_launch(void* const* d_in, const int* in_sizes, int n_in,
                              void* d_out, int out_size)
{
    const float* q      = (const float*)d_in[0];
    const float* k      = (const float*)d_in[1];
    const float* v      = (const float*)d_in[2];
    const float* Wq     = (const float*)d_in[3];
    const float* Wk     = (const float*)d_in[4];
    const float* Wv     = (const float*)d_in[5];
    const float* fc_w   = (const float*)d_in[6];
    const float* fc_b   = (const float*)d_in[7];
    const float* gate_w = (const float*)d_in[8];
    const float* gate_b = (const float*)d_in[9];

    float* out  = (float*)d_out;
    float* attn = out + (size_t)BATCH * NBLK * DMODEL;      // second output
    float* scal = out + (size_t)out_size - 1;               // trailing scalar

    proj_kernel<<<dim3(4, 2, 192), 256>>>(q, k, v, Wq, Wk, Wv);
    attn_kernel<<<2048, 64>>>(attn);
    fcgate_kernel<<<dim3(128, 8), 256>>>(fc_w, fc_b, gate_w, gate_b, out, scal);
}